// round 10
// baseline (speedup 1.0000x reference)
#include <cuda_runtime.h>
#include <cuda_fp16.h>
#include <cstdint>
#include <math.h>

// Shapes fixed by reference
#define BATCH 4
#define SEQ   2048
#define DIM   1024

// ---------------- scratch (device globals; allocation-free rule) ------------
__device__ __half g_Qh [(long)BATCH * SEQ * DIM];   // [8192,1024]
__device__ __half g_Kh [(long)BATCH * SEQ * DIM];   // [8192,1024]
__device__ __half g_Vth[(long)BATCH * DIM * SEQ];   // per batch [1024,2048] (V^T)
__device__ float  g_S  [(long)BATCH * SEQ * SEQ];   // scores (fp32)
__device__ __half g_P  [(long)BATCH * SEQ * SEQ];   // softmax probs (fp16)
__device__ __half g_xh [(long)BATCH * SEQ * DIM];   // x in fp16
__device__ __half g_Wh [3L * DIM * DIM];            // Wq,Wk,Wv in fp16

// ---------------- helpers ----------------
__device__ __forceinline__ uint32_t smem_u32(const void* p) {
    uint32_t a;
    asm("{ .reg .u64 t; cvta.to.shared.u64 t, %1; cvt.u32.u64 %0, t; }" : "=r"(a) : "l"(p));
    return a;
}
__device__ __forceinline__ void cp_async16(uint32_t dst, const void* src) {
    asm volatile("cp.async.cg.shared.global [%0], [%1], 16;" :: "r"(dst), "l"(src));
}
#define CP_COMMIT() asm volatile("cp.async.commit_group;" ::: "memory")
#define CP_WAIT(n)  asm volatile("cp.async.wait_group %0;" :: "n"(n) : "memory")

// m16n8k16 fp16 MMA, f32 accumulate (valid on plain compute_100 target)
__device__ __forceinline__ void mma_f16(float* d, const uint32_t* a, const uint32_t* b) {
    asm volatile(
        "mma.sync.aligned.m16n8k16.row.col.f32.f16.f16.f32 "
        "{%0,%1,%2,%3}, {%4,%5,%6,%7}, {%8,%9}, {%0,%1,%2,%3};\n"
        : "+f"(d[0]), "+f"(d[1]), "+f"(d[2]), "+f"(d[3])
        : "r"(a[0]), "r"(a[1]), "r"(a[2]), "r"(a[3]), "r"(b[0]), "r"(b[1]));
}
__device__ __forceinline__ void ldsm_x4(uint32_t* r, uint32_t addr) {
    asm volatile("ldmatrix.sync.aligned.m8n8.x4.shared.b16 {%0,%1,%2,%3}, [%4];"
                 : "=r"(r[0]), "=r"(r[1]), "=r"(r[2]), "=r"(r[3]) : "r"(addr));
}

// ---------------- fp16 mma.sync NT GEMM (256x256 CTA, 64x64 warp) -----------
// C[M,N] = alpha * A[M,K] @ B[N,K]^T; A,B fp16 row-major (K contiguous).
// Batched via blockIdx.z (strides in elements). CTA tile 256x256, K tile 64
// halves (128B rows), 3-stage cp.async pipeline, 16 warps (4x4), warp 64x64.
#define BM 256
#define BN 256
#define BKH 64                           // K-tile in halves (128 bytes)
#define STAGES 3
#define ROWB 144                         // padded row stride in bytes (128+16)
#define TILE_B (BM * ROWB)               // bytes per stage tile (36864)
#define SMEM_TOTAL (2 * STAGES * TILE_B) // 221,184 B
#define NTHR 512

__global__ __launch_bounds__(NTHR, 1)
void gemm_hf(const __half* __restrict__ A, const __half* __restrict__ B,
             void* __restrict__ C, int K, int N,
             long sA, long sB, long sC, float alpha, int out_half)
{
    extern __shared__ char smem[];
    const uint32_t sbase = smem_u32(smem);
    const int tid = threadIdx.x;
    const int wid = tid >> 5;
    const int lid = tid & 31;
    const int warpM = wid >> 2;          // 0..3 -> 64-row slab
    const int warpN = wid & 3;           // 0..3 -> 64-col slab
    const int qrow = lid >> 2;           // 0..7
    const int qcol = lid & 3;            // 0..3

    const char* Ab = (const char*)(A + (long)blockIdx.z * sA + (long)blockIdx.y * BM * K);
    const char* Bb = (const char*)(B + (long)blockIdx.z * sB + (long)blockIdx.x * BN * K);
    const long  Kb = (long)K * 2;        // row pitch bytes
    const int   NK = K / BKH;

    // ldmatrix per-thread offsets (within stage tile), ks excluded:
    // A x4 tile mt: lane -> row = warpM*64 + mt*16 + (lid&15), colByte=(lid>>4)*16
    uint32_t aoff[4];
#pragma unroll
    for (int mt = 0; mt < 4; mt++)
        aoff[mt] = (uint32_t)((warpM * 64 + mt * 16 + (lid & 15)) * ROWB + (lid >> 4) * 16);
    // B x4 pair p (covers nt=2p,2p+1): lane -> n = warpN*64 + p*16 + (lid>>4)*8 + (lid&7),
    //   colByte = ((lid>>3)&1)*16
    uint32_t boff[4];
#pragma unroll
    for (int p = 0; p < 4; p++)
        boff[p] = (uint32_t)((warpN * 64 + p * 16 + (lid >> 4) * 8 + (lid & 7)) * ROWB
                             + ((lid >> 3) & 1) * 16);

    // loader: 256 rows x 8 chunks(16B) per array = 2048 chunks; 512 thr x 4 each
    auto load_tile = [&](int kt, int slot) {
        const uint32_t sa = sbase + slot * TILE_B;
        const uint32_t sb = sbase + (STAGES + slot) * TILE_B;
        const long kofs = (long)kt * 128;             // 64 halves = 128B
#pragma unroll
        for (int j = 0; j < 4; j++) {
            const int cid = tid + j * NTHR;
            const int r  = cid >> 3;
            const int cc = (cid & 7) * 16;
            const uint32_t so = (uint32_t)(r * ROWB + cc);
            cp_async16(sa + so, Ab + (long)r * Kb + kofs + cc);
            cp_async16(sb + so, Bb + (long)r * Kb + kofs + cc);
        }
    };

    float acc[4][8][4];
#pragma unroll
    for (int mt = 0; mt < 4; mt++)
#pragma unroll
        for (int nt = 0; nt < 8; nt++)
#pragma unroll
            for (int i = 0; i < 4; i++) acc[mt][nt][i] = 0.0f;

#pragma unroll
    for (int s = 0; s < STAGES - 1; s++) { load_tile(s, s); CP_COMMIT(); }

    for (int kt = 0; kt < NK; kt++) {
        const int slot = kt % STAGES;
        CP_WAIT(STAGES - 2);
        __syncthreads();

        const int pf = kt + STAGES - 1;
        if (pf < NK) load_tile(pf, pf % STAGES);
        CP_COMMIT();

        const uint32_t As = sbase + slot * TILE_B;
        const uint32_t Bs = sbase + (STAGES + slot) * TILE_B;
#pragma unroll
        for (int ks = 0; ks < BKH / 16; ks++) {
            const uint32_t kb = ks * 32;              // 16 halves = 32 bytes
            uint32_t a[4][4], b[4][4];   // b[p] = frags for nt=2p (k0,k8), nt=2p+1 (k0,k8)
#pragma unroll
            for (int mt = 0; mt < 4; mt++) ldsm_x4(a[mt], As + aoff[mt] + kb);
#pragma unroll
            for (int p = 0; p < 4; p++)   ldsm_x4(b[p], Bs + boff[p] + kb);
#pragma unroll
            for (int mt = 0; mt < 4; mt++)
#pragma unroll
                for (int nt = 0; nt < 8; nt++)
                    mma_f16(acc[mt][nt], a[mt], &b[nt >> 1][(nt & 1) * 2]);
        }
        // next iteration's __syncthreads() protects slot reuse
    }

    // epilogue: c0,c1 at (row, col..col+1), c2,c3 at (row+8, ...)
#pragma unroll
    for (int mt = 0; mt < 4; mt++) {
        const long r0 = (long)blockIdx.y * BM + warpM * 64 + mt * 16 + qrow;
#pragma unroll
        for (int nt = 0; nt < 8; nt++) {
            const long c0 = (long)blockIdx.x * BN + warpN * 64 + nt * 8 + qcol * 2;
            float lo0 = acc[mt][nt][0] * alpha, lo1 = acc[mt][nt][1] * alpha;
            float hi0 = acc[mt][nt][2] * alpha, hi1 = acc[mt][nt][3] * alpha;
            if (out_half) {
                __half* Cb = (__half*)C + (long)blockIdx.z * sC;
                *(__half2*)(Cb + r0 * N + c0)       = __floats2half2_rn(lo0, lo1);
                *(__half2*)(Cb + (r0 + 8) * N + c0) = __floats2half2_rn(hi0, hi1);
            } else {
                float* Cb = (float*)C + (long)blockIdx.z * sC;
                float2 lo; lo.x = lo0; lo.y = lo1;
                float2 hi; hi.x = hi0; hi.y = hi1;
                *(float2*)(Cb + r0 * N + c0)       = lo;
                *(float2*)(Cb + (r0 + 8) * N + c0) = hi;
            }
        }
    }
}

// ---------------- f32 -> f16 convert ----------------
__global__ __launch_bounds__(256)
void convert_f16(const float* __restrict__ in, __half* __restrict__ out)
{
    const long i = ((long)blockIdx.x * 256 + threadIdx.x) * 4;
    float4 v = *(const float4*)(in + i);
    __half2 h0 = __floats2half2_rn(v.x, v.y);
    __half2 h1 = __floats2half2_rn(v.z, v.w);
    uint2 u;
    u.x = *(uint32_t*)&h0;
    u.y = *(uint32_t*)&h1;
    *(uint2*)(out + i) = u;
}

// ---------------- row softmax: fp32 scores in, fp16 probs out ---------------
__global__ __launch_bounds__(256)
void softmax_rows(const float* __restrict__ S, __half* __restrict__ P, int n)
{
    const float* row = S + (long)blockIdx.x * n;
    __half* prow = P + (long)blockIdx.x * n;
    const int tid = threadIdx.x;
    __shared__ float red[8];
    __shared__ float sm, ssum;

    float m = -1e30f;
    for (int i = tid * 4; i < n; i += 1024) {
        float4 v = *(const float4*)(row + i);
        m = fmaxf(m, fmaxf(fmaxf(v.x, v.y), fmaxf(v.z, v.w)));
    }
#pragma unroll
    for (int o = 16; o; o >>= 1) m = fmaxf(m, __shfl_xor_sync(0xffffffffu, m, o));
    if ((tid & 31) == 0) red[tid >> 5] = m;
    __syncthreads();
    if (tid < 32) {
        float v = (tid < 8) ? red[tid] : -1e30f;
#pragma unroll
        for (int o = 4; o; o >>= 1) v = fmaxf(v, __shfl_xor_sync(0xffffffffu, v, o));
        if (tid == 0) sm = v;
    }
    __syncthreads();
    const float mm = sm;

    float s = 0.0f;
    for (int i = tid * 4; i < n; i += 1024) {
        float4 v = *(const float4*)(row + i);
        s += __expf(v.x - mm) + __expf(v.y - mm) + __expf(v.z - mm) + __expf(v.w - mm);
    }
#pragma unroll
    for (int o = 16; o; o >>= 1) s += __shfl_xor_sync(0xffffffffu, s, o);
    if ((tid & 31) == 0) red[tid >> 5] = s;
    __syncthreads();
    if (tid < 32) {
        float v = (tid < 8) ? red[tid] : 0.0f;
#pragma unroll
        for (int o = 4; o; o >>= 1) v += __shfl_xor_sync(0xffffffffu, v, o);
        if (tid == 0) ssum = v;
    }
    __syncthreads();
    const float inv = 1.0f / ssum;

    for (int i = tid * 4; i < n; i += 1024) {
        float4 v = *(const float4*)(row + i);
        __half2 h0 = __floats2half2_rn(__expf(v.x - mm) * inv, __expf(v.y - mm) * inv);
        __half2 h1 = __floats2half2_rn(__expf(v.z - mm) * inv, __expf(v.w - mm) * inv);
        uint2 u;
        u.x = *(uint32_t*)&h0;
        u.y = *(uint32_t*)&h1;
        *(uint2*)(prow + i) = u;
    }
}

// ---------------- launcher ----------------
extern "C" void kernel_launch(void* const* d_in, const int* in_sizes, int n_in,
                              void* d_out, int out_size)
{
    (void)in_sizes; (void)n_in; (void)out_size;
    const float* x  = (const float*)d_in[0];
    const float* Wk = (const float*)d_in[1];
    const float* Wq = (const float*)d_in[2];
    const float* Wv = (const float*)d_in[3];
    float* out = (float*)d_out;

    __half *Qh, *Kh, *Vth, *P, *xh, *Wh;
    float *S;
    cudaGetSymbolAddress((void**)&Qh,  g_Qh);
    cudaGetSymbolAddress((void**)&Kh,  g_Kh);
    cudaGetSymbolAddress((void**)&Vth, g_Vth);
    cudaGetSymbolAddress((void**)&S,   g_S);
    cudaGetSymbolAddress((void**)&P,   g_P);
    cudaGetSymbolAddress((void**)&xh,  g_xh);
    cudaGetSymbolAddress((void**)&Wh,  g_Wh);

    cudaFuncSetAttribute(gemm_hf, cudaFuncAttributeMaxDynamicSharedMemorySize, SMEM_TOTAL);

    const long nX = (long)BATCH * SEQ * DIM;
    const long nW = (long)DIM * DIM;
    __half* Wq_h = Wh + 0 * nW;
    __half* Wk_h = Wh + 1 * nW;
    __half* Wv_h = Wh + 2 * nW;

    // 0) convert inputs to fp16
    convert_f16<<<(int)(nX / 1024), 256>>>(x,  xh);
    convert_f16<<<(int)(nW / 1024), 256>>>(Wq, Wq_h);
    convert_f16<<<(int)(nW / 1024), 256>>>(Wk, Wk_h);
    convert_f16<<<(int)(nW / 1024), 256>>>(Wv, Wv_h);

    const long sX = (long)SEQ * DIM;
    const long sS = (long)SEQ * SEQ;
    const long sV = (long)DIM * SEQ;

    // 1) Q = x @ Wq^T, K = x @ Wk^T   (M=8192, N=1024, K=1024) -> fp16
    {
        dim3 g(DIM / BN, (BATCH * SEQ) / BM, 1);
        gemm_hf<<<g, NTHR, SMEM_TOTAL>>>(xh, Wq_h, Qh, DIM, DIM, 0, 0, 0, 1.0f, 1);
        gemm_hf<<<g, NTHR, SMEM_TOTAL>>>(xh, Wk_h, Kh, DIM, DIM, 0, 0, 0, 1.0f, 1);
    }
    // 2) Vt[b] = Wv @ x[b]^T          (M=1024, N=2048, K=1024) -> fp16
    {
        dim3 g(SEQ / BN, DIM / BM, BATCH);
        gemm_hf<<<g, NTHR, SMEM_TOTAL>>>(Wv_h, xh, Vth, DIM, SEQ, 0, sX, sV, 1.0f, 1);
    }
    // 3) S[b] = (Q[b] @ K[b]^T) / 32  (M=2048, N=2048, K=1024) -> fp32
    {
        dim3 g(SEQ / BN, SEQ / BM, BATCH);
        gemm_hf<<<g, NTHR, SMEM_TOTAL>>>(Qh, Kh, S, DIM, SEQ, sX, sX, sS, 1.0f / 32.0f, 0);
    }
    // 4) row softmax -> fp16 probs
    softmax_rows<<<BATCH * SEQ, 256>>>(S, P, SEQ);

    // 5) out[b] = P[b] @ Vt[b]^T      (M=2048, N=1024, K=2048) -> fp32 d_out
    {
        dim3 g(DIM / BN, SEQ / BM, BATCH);
        gemm_hf<<<g, NTHR, SMEM_TOTAL>>>(P, Vth, out, SEQ, DIM, sS, sV, sX, 1.0f, 0);
    }
}

// round 16
// speedup vs baseline: 2.7595x; 2.7595x over previous
#include <cuda_runtime.h>
#include <cuda_fp16.h>
#include <cstdint>
#include <math.h>

// Shapes fixed by reference
#define BATCH 4
#define SEQ   2048
#define DIM   1024

// ---------------- scratch (device globals; allocation-free rule) ------------
__device__ __half g_Qh [(long)BATCH * SEQ * DIM];   // [8192,1024]
__device__ __half g_Kh [(long)BATCH * SEQ * DIM];   // [8192,1024]
__device__ __half g_Vth[(long)BATCH * DIM * SEQ];   // per batch [1024,2048] (V^T)
__device__ float  g_S  [(long)BATCH * SEQ * SEQ];   // scores (fp32)
__device__ __half g_P  [(long)BATCH * SEQ * SEQ];   // softmax probs (fp16)
__device__ __half g_xh [(long)BATCH * SEQ * DIM];   // x in fp16
__device__ __half g_Wh [3L * DIM * DIM];            // Wq,Wk,Wv in fp16

// ---------------- helpers ----------------
__device__ __forceinline__ uint32_t smem_u32(const void* p) {
    uint32_t a;
    asm("{ .reg .u64 t; cvta.to.shared.u64 t, %1; cvt.u32.u64 %0, t; }" : "=r"(a) : "l"(p));
    return a;
}
__device__ __forceinline__ void cp_async16(uint32_t dst, const void* src) {
    asm volatile("cp.async.cg.shared.global [%0], [%1], 16;" :: "r"(dst), "l"(src));
}
#define CP_COMMIT() asm volatile("cp.async.commit_group;" ::: "memory")
#define CP_WAIT(n)  asm volatile("cp.async.wait_group %0;" :: "n"(n) : "memory")

// m16n8k16 fp16 MMA, f32 accumulate (valid on plain compute_100 target)
__device__ __forceinline__ void mma_f16(float* d, const uint32_t* a, const uint32_t* b) {
    asm volatile(
        "mma.sync.aligned.m16n8k16.row.col.f32.f16.f16.f32 "
        "{%0,%1,%2,%3}, {%4,%5,%6,%7}, {%8,%9}, {%0,%1,%2,%3};\n"
        : "+f"(d[0]), "+f"(d[1]), "+f"(d[2]), "+f"(d[3])
        : "r"(a[0]), "r"(a[1]), "r"(a[2]), "r"(a[3]), "r"(b[0]), "r"(b[1]));
}
__device__ __forceinline__ void ldsm_x4(uint32_t* r, uint32_t addr) {
    asm volatile("ldmatrix.sync.aligned.m8n8.x4.shared.b16 {%0,%1,%2,%3}, [%4];"
                 : "=r"(r[0]), "=r"(r[1]), "=r"(r[2]), "=r"(r[3]) : "r"(addr));
}

// ---------------- fp16 mma.sync NT GEMM (ldmatrix fragments) ----------------
// C[M,N] = alpha * A[M,K] @ B[N,K]^T; A,B fp16 row-major (K contiguous).
// Batched via blockIdx.z (strides in elements). CTA tile 128x128, K tile 64
// halves (128B rows), 3-stage cp.async pipeline, 8 warps (2x4), warp 64x32.
#define BM 128
#define BN 128
#define BKH 64                           // K-tile in halves (128 bytes)
#define STAGES 3
#define ROWB 144                         // padded row stride in bytes (128+16)
#define TILE_B (128 * ROWB)              // bytes per stage tile (18432)
#define SMEM_TOTAL (2 * STAGES * TILE_B) // 110,592 B

__global__ __launch_bounds__(256, 2)
void gemm_hf(const __half* __restrict__ A, const __half* __restrict__ B,
             void* __restrict__ C, int K, int N,
             long sA, long sB, long sC, float alpha, int out_half)
{
    extern __shared__ char smem[];
    const uint32_t sbase = smem_u32(smem);
    const int tid = threadIdx.x;
    const int wid = tid >> 5;
    const int lid = tid & 31;
    const int warpM = wid >> 2;          // 0..1  -> 64-row slab
    const int warpN = wid & 3;           // 0..3  -> 32-col slab
    const int qrow = lid >> 2;           // 0..7
    const int qcol = lid & 3;            // 0..3

    const char* Ab = (const char*)(A + (long)blockIdx.z * sA + (long)blockIdx.y * BM * K);
    const char* Bb = (const char*)(B + (long)blockIdx.z * sB + (long)blockIdx.x * BN * K);
    const long  Kb = (long)K * 2;        // row pitch bytes
    const int   NK = K / BKH;

    // ldmatrix per-thread address offsets (within a stage tile), excluding ks:
    uint32_t aoff[4];
#pragma unroll
    for (int mt = 0; mt < 4; mt++)
        aoff[mt] = (uint32_t)((warpM * 64 + mt * 16 + (lid & 15)) * ROWB + (lid >> 4) * 16);
    uint32_t boff[2];
#pragma unroll
    for (int p = 0; p < 2; p++)
        boff[p] = (uint32_t)((warpN * 32 + p * 16 + (lid >> 4) * 8 + (lid & 7)) * ROWB
                             + ((lid >> 3) & 1) * 16);

    // loader: 128 rows x 8 chunks(16B) per tile; cid = tid + j*256
    auto load_tile = [&](int kt, int slot) {
        const uint32_t sa = sbase + slot * TILE_B;
        const uint32_t sb = sbase + (STAGES + slot) * TILE_B;
        const long kofs = (long)kt * 128;             // 64 halves = 128B
#pragma unroll
        for (int j = 0; j < 4; j++) {
            const int cid = tid + j * 256;
            const int r  = cid >> 3;
            const int cc = (cid & 7) * 16;
            const uint32_t so = (uint32_t)(r * ROWB + cc);
            cp_async16(sa + so, Ab + (long)r * Kb + kofs + cc);
            cp_async16(sb + so, Bb + (long)r * Kb + kofs + cc);
        }
    };

    float acc[4][4][4];
#pragma unroll
    for (int mt = 0; mt < 4; mt++)
#pragma unroll
        for (int nt = 0; nt < 4; nt++)
#pragma unroll
            for (int i = 0; i < 4; i++) acc[mt][nt][i] = 0.0f;

#pragma unroll
    for (int s = 0; s < STAGES - 1; s++) { load_tile(s, s); CP_COMMIT(); }

    for (int kt = 0; kt < NK; kt++) {
        const int slot = kt % STAGES;
        CP_WAIT(STAGES - 2);
        __syncthreads();

        const int pf = kt + STAGES - 1;
        if (pf < NK) load_tile(pf, pf % STAGES);
        CP_COMMIT();

        const uint32_t As = sbase + slot * TILE_B;
        const uint32_t Bs = sbase + (STAGES + slot) * TILE_B;
#pragma unroll
        for (int ks = 0; ks < BKH / 16; ks++) {
            const uint32_t kb = ks * 32;              // 16 halves = 32 bytes
            uint32_t a[4][4], b[2][4];
#pragma unroll
            for (int mt = 0; mt < 4; mt++) ldsm_x4(a[mt], As + aoff[mt] + kb);
#pragma unroll
            for (int p = 0; p < 2; p++)   ldsm_x4(b[p], Bs + boff[p] + kb);
#pragma unroll
            for (int mt = 0; mt < 4; mt++)
#pragma unroll
                for (int nt = 0; nt < 4; nt++)
                    mma_f16(acc[mt][nt], a[mt], &b[nt >> 1][(nt & 1) * 2]);
        }
        // next iteration's __syncthreads() protects slot reuse
    }

    // epilogue
#pragma unroll
    for (int mt = 0; mt < 4; mt++) {
        const long r0 = (long)blockIdx.y * BM + warpM * 64 + mt * 16 + qrow;
#pragma unroll
        for (int nt = 0; nt < 4; nt++) {
            const long c0 = (long)blockIdx.x * BN + warpN * 32 + nt * 8 + qcol * 2;
            float lo0 = acc[mt][nt][0] * alpha, lo1 = acc[mt][nt][1] * alpha;
            float hi0 = acc[mt][nt][2] * alpha, hi1 = acc[mt][nt][3] * alpha;
            if (out_half) {
                __half* Cb = (__half*)C + (long)blockIdx.z * sC;
                *(__half2*)(Cb + r0 * N + c0)       = __floats2half2_rn(lo0, lo1);
                *(__half2*)(Cb + (r0 + 8) * N + c0) = __floats2half2_rn(hi0, hi1);
            } else {
                float* Cb = (float*)C + (long)blockIdx.z * sC;
                float2 lo; lo.x = lo0; lo.y = lo1;
                float2 hi; hi.x = hi0; hi.y = hi1;
                *(float2*)(Cb + r0 * N + c0)       = lo;
                *(float2*)(Cb + (r0 + 8) * N + c0) = hi;
            }
        }
    }
}

// ---------------- fused f32 -> f16 convert (x + Wk + Wq + Wv in ONE launch) --
// grid: [0, 8192) -> x ; [8192, 9216) Wk ; [9216,10240) Wq ; [10240,11264) Wv
__global__ __launch_bounds__(256)
void convert_all(const float* __restrict__ x,  __half* __restrict__ xh,
                 const float* __restrict__ Wk, __half* __restrict__ Wkh,
                 const float* __restrict__ Wq, __half* __restrict__ Wqh,
                 const float* __restrict__ Wv, __half* __restrict__ Wvh)
{
    const int bid = blockIdx.x;
    const float* src;
    __half* dst;
    long base;
    if (bid < 8192)       { src = x;  dst = xh;  base = (long)bid * 1024; }
    else if (bid < 9216)  { src = Wk; dst = Wkh; base = (long)(bid - 8192) * 1024; }
    else if (bid < 10240) { src = Wq; dst = Wqh; base = (long)(bid - 9216) * 1024; }
    else                  { src = Wv; dst = Wvh; base = (long)(bid - 10240) * 1024; }

    const long i = base + (long)threadIdx.x * 4;
    float4 v = *(const float4*)(src + i);
    __half2 h0 = __floats2half2_rn(v.x, v.y);
    __half2 h1 = __floats2half2_rn(v.z, v.w);
    uint2 u;
    u.x = *(uint32_t*)&h0;
    u.y = *(uint32_t*)&h1;
    *(uint2*)(dst + i) = u;
}

// ---------------- row softmax: single-pass, register-resident ---------------
// Row = 2048 floats; 256 threads x 2 float4 (8 floats) each = exactly 2048.
__global__ __launch_bounds__(256)
void softmax_rows(const float* __restrict__ S, __half* __restrict__ P)
{
    const float* row = S + (long)blockIdx.x * SEQ;
    __half* prow = P + (long)blockIdx.x * SEQ;
    const int tid = threadIdx.x;
    __shared__ float red[8];
    __shared__ float sm, ssum;

    float4 v[2];
    float m = -1e30f;
#pragma unroll
    for (int j = 0; j < 2; j++) {
        v[j] = *(const float4*)(row + tid * 4 + j * 1024);
        m = fmaxf(m, fmaxf(fmaxf(v[j].x, v[j].y), fmaxf(v[j].z, v[j].w)));
    }
#pragma unroll
    for (int o = 16; o; o >>= 1) m = fmaxf(m, __shfl_xor_sync(0xffffffffu, m, o));
    if ((tid & 31) == 0) red[tid >> 5] = m;
    __syncthreads();
    if (tid < 32) {
        float t = (tid < 8) ? red[tid] : -1e30f;
#pragma unroll
        for (int o = 4; o; o >>= 1) t = fmaxf(t, __shfl_xor_sync(0xffffffffu, t, o));
        if (tid == 0) sm = t;
    }
    __syncthreads();
    const float mm = sm;

    float s = 0.0f;
#pragma unroll
    for (int j = 0; j < 2; j++) {
        v[j].x = __expf(v[j].x - mm);
        v[j].y = __expf(v[j].y - mm);
        v[j].z = __expf(v[j].z - mm);
        v[j].w = __expf(v[j].w - mm);
        s += v[j].x + v[j].y + v[j].z + v[j].w;
    }
#pragma unroll
    for (int o = 16; o; o >>= 1) s += __shfl_xor_sync(0xffffffffu, s, o);
    if ((tid & 31) == 0) red[tid >> 5] = s;
    __syncthreads();
    if (tid < 32) {
        float t = (tid < 8) ? red[tid] : 0.0f;
#pragma unroll
        for (int o = 4; o; o >>= 1) t += __shfl_xor_sync(0xffffffffu, t, o);
        if (tid == 0) ssum = t;
    }
    __syncthreads();
    const float inv = 1.0f / ssum;

#pragma unroll
    for (int j = 0; j < 2; j++) {
        __half2 h0 = __floats2half2_rn(v[j].x * inv, v[j].y * inv);
        __half2 h1 = __floats2half2_rn(v[j].z * inv, v[j].w * inv);
        uint2 u;
        u.x = *(uint32_t*)&h0;
        u.y = *(uint32_t*)&h1;
        *(uint2*)(prow + tid * 4 + j * 1024) = u;
    }
}

// ---------------- launcher ----------------
extern "C" void kernel_launch(void* const* d_in, const int* in_sizes, int n_in,
                              void* d_out, int out_size)
{
    (void)in_sizes; (void)n_in; (void)out_size;
    const float* x  = (const float*)d_in[0];
    const float* Wk = (const float*)d_in[1];
    const float* Wq = (const float*)d_in[2];
    const float* Wv = (const float*)d_in[3];
    float* out = (float*)d_out;

    __half *Qh, *Kh, *Vth, *P, *xh, *Wh;
    float *S;
    cudaGetSymbolAddress((void**)&Qh,  g_Qh);
    cudaGetSymbolAddress((void**)&Kh,  g_Kh);
    cudaGetSymbolAddress((void**)&Vth, g_Vth);
    cudaGetSymbolAddress((void**)&S,   g_S);
    cudaGetSymbolAddress((void**)&P,   g_P);
    cudaGetSymbolAddress((void**)&xh,  g_xh);
    cudaGetSymbolAddress((void**)&Wh,  g_Wh);

    cudaFuncSetAttribute(gemm_hf, cudaFuncAttributeMaxDynamicSharedMemorySize, SMEM_TOTAL);

    const long nW = (long)DIM * DIM;
    __half* Wq_h = Wh + 0 * nW;
    __half* Wk_h = Wh + 1 * nW;
    __half* Wv_h = Wh + 2 * nW;

    const long sX = (long)SEQ * DIM;
    const long sS = (long)SEQ * SEQ;
    const long sV = (long)DIM * SEQ;

    // Launch order puts the SCORE GEMM at position 4 (ncu captures launch #4).
    // (1) fused converts
    convert_all<<<11264, 256>>>(x, xh, Wk, Wk_h, Wq, Wq_h, Wv, Wv_h);

    // (2) Q = x @ Wq^T, (3) K = x @ Wk^T   (M=8192, N=1024, K=1024) -> fp16
    {
        dim3 g(DIM / BN, (BATCH * SEQ) / BM, 1);
        gemm_hf<<<g, 256, SMEM_TOTAL>>>(xh, Wq_h, Qh, DIM, DIM, 0, 0, 0, 1.0f, 1);
        gemm_hf<<<g, 256, SMEM_TOTAL>>>(xh, Wk_h, Kh, DIM, DIM, 0, 0, 0, 1.0f, 1);
    }
    // (4) S[b] = (Q[b] @ K[b]^T) / 32  (M=2048, N=2048, K=1024) -> fp32
    {
        dim3 g(SEQ / BN, SEQ / BM, BATCH);
        gemm_hf<<<g, 256, SMEM_TOTAL>>>(Qh, Kh, S, DIM, SEQ, sX, sX, sS, 1.0f / 32.0f, 0);
    }
    // (5) Vt[b] = Wv @ x[b]^T          (M=1024, N=2048, K=1024) -> fp16
    {
        dim3 g(SEQ / BN, DIM / BM, BATCH);
        gemm_hf<<<g, 256, SMEM_TOTAL>>>(Wv_h, xh, Vth, DIM, SEQ, 0, sX, sV, 1.0f, 1);
    }
    // (6) row softmax (register-resident) -> fp16 probs
    softmax_rows<<<BATCH * SEQ, 256>>>(S, P);

    // (7) out[b] = P[b] @ Vt[b]^T      (M=2048, N=1024, K=2048) -> fp32 d_out
    {
        dim3 g(DIM / BN, SEQ / BM, BATCH);
        gemm_hf<<<g, 256, SMEM_TOTAL>>>(P, Vth, out, SEQ, DIM, sS, sV, sX, 1.0f, 0);
    }
}